// round 1
// baseline (speedup 1.0000x reference)
#include <cuda_runtime.h>
#include <math.h>

#define Bb 8
#define Tt 8192
#define Ss 8192
#define Ff 64
#define Dd 64
#define Mm 128          // feature pairs; 2M = 256 features
#define TWO_M 256
#define EPSf 1e-9f
#define CHUNKS 32
#define ROWS_ITER 8

// scratch: kv[b][m][d], d in 0..64 (last = normalizer column)
__device__ float g_kv[Bb * TWO_M * (Dd + 1)];

__global__ void zero_kv_kernel() {
    int i = blockIdx.x * blockDim.x + threadIdx.x;
    if (i < Bb * TWO_M * (Dd + 1)) g_kv[i] = 0.0f;
}

// ---------------------------------------------------------------------------
// Kernel A: kv[b][m][d] = sum_s phi_k[s][m] * v1[s][d]
// Thread owns feature m (omega row in regs), accumulates 65 floats in regs
// over a chunk of S rows, then atomically adds into g_kv.
// ---------------------------------------------------------------------------
__global__ __launch_bounds__(256, 1)
void kv_kernel(const float* __restrict__ key,
               const float* __restrict__ value,
               const float* __restrict__ omega) {
    const int b     = blockIdx.y;
    const int chunk = blockIdx.x;
    const int tid   = threadIdx.x;          // m = tid in [0, 256)
    const int mrow  = tid & 127;
    const float sign = (tid < 128) ? 1.0f : -1.0f;

    __shared__ float4 ksh[ROWS_ITER][16];
    __shared__ float4 vsh[ROWS_ITER][16];
    __shared__ float  ssh[ROWS_ITER];

    // omega row -> registers
    float om[64];
    const float4* og = (const float4*)(omega + mrow * Ff);
    #pragma unroll
    for (int j = 0; j < 16; j++) {
        float4 o4 = og[j];
        om[4*j+0] = o4.x; om[4*j+1] = o4.y; om[4*j+2] = o4.z; om[4*j+3] = o4.w;
    }

    float acc[Dd + 1];
    #pragma unroll
    for (int d = 0; d <= Dd; d++) acc[d] = 0.0f;

    const int rows_per_block = Ss / CHUNKS;      // 256
    const int row0 = chunk * rows_per_block;
    const float* kb = key   + ((size_t)b * Ss) * Ff;
    const float* vb = value + ((size_t)b * Ss) * Dd;

    for (int r0 = 0; r0 < rows_per_block; r0 += ROWS_ITER) {
        // cooperative load: 8 rows of k (threads 0..127) and v (threads 128..255)
        {
            int li = tid & 127;
            int lr = li >> 4;
            int lj = li & 15;
            size_t row = (size_t)(row0 + r0 + lr);
            if (tid < 128)
                ksh[lr][lj] = ((const float4*)(kb + row * Ff))[lj];
            else
                vsh[lr][lj] = ((const float4*)(vb + row * Dd))[lj];
        }
        __syncthreads();
        if (tid < ROWS_ITER) {
            float s = 0.0f;
            #pragma unroll
            for (int j = 0; j < 16; j++) {
                float4 x = ksh[tid][j];
                s += x.x*x.x + x.y*x.y + x.z*x.z + x.w*x.w;
            }
            ssh[tid] = 0.5f * s;
        }
        __syncthreads();

        #pragma unroll
        for (int r = 0; r < ROWS_ITER; r++) {
            float d0 = 0.f, d1 = 0.f, d2 = 0.f, d3 = 0.f;
            #pragma unroll
            for (int j = 0; j < 16; j++) {
                float4 x = ksh[r][j];                    // broadcast LDS
                d0 += om[4*j+0] * x.x;
                d1 += om[4*j+1] * x.y;
                d2 += om[4*j+2] * x.z;
                d3 += om[4*j+3] * x.w;
            }
            float dot = (d0 + d1) + (d2 + d3);
            float phi = __expf(sign * dot - ssh[r]) + EPSf;
            #pragma unroll
            for (int j = 0; j < 16; j++) {
                float4 v = vsh[r][j];                    // broadcast LDS
                acc[4*j+0] += phi * v.x;
                acc[4*j+1] += phi * v.y;
                acc[4*j+2] += phi * v.z;
                acc[4*j+3] += phi * v.w;
            }
            acc[Dd] += phi;
        }
        __syncthreads();
    }

    float* kvb = g_kv + ((size_t)b * TWO_M + tid) * (Dd + 1);
    #pragma unroll
    for (int d = 0; d <= Dd; d++) atomicAdd(kvb + d, acc[d]);
}

// ---------------------------------------------------------------------------
// Kernel B: out[b][t][d] = (phi_q[t] . kv[:, d]) / (phi_q[t] . kv[:, 64])
// Thread owns one output row t. kv (padded to 68 floats/row) + omega in
// dynamic shared (all reads are warp-uniform broadcasts).
// ---------------------------------------------------------------------------
#define KV_PAD 68

extern __shared__ float sh_dyn[];

__global__ __launch_bounds__(256, 1)
void out_kernel(const float* __restrict__ query,
                const float* __restrict__ omega,
                float* __restrict__ out) {
    const int b = blockIdx.y;
    const int t = blockIdx.x * 256 + threadIdx.x;

    float* kvs = sh_dyn;                 // 256 * 68 floats
    float* osh = sh_dyn + TWO_M * KV_PAD; // 128 * 64 floats

    const float* kvg = g_kv + (size_t)b * TWO_M * (Dd + 1);
    for (int i = threadIdx.x; i < TWO_M * (Dd + 1); i += 256) {
        int m = i / (Dd + 1);
        int d = i - m * (Dd + 1);
        kvs[m * KV_PAD + d] = kvg[i];
    }
    for (int i = threadIdx.x; i < Mm * Ff; i += 256) osh[i] = omega[i];
    __syncthreads();

    // q row -> registers, plus square-sum
    const float* qrow = query + ((size_t)b * Tt + t) * Ff;
    float q[64];
    float ss = 0.0f;
    #pragma unroll
    for (int j = 0; j < 16; j++) {
        float4 x = ((const float4*)qrow)[j];
        q[4*j+0] = x.x; q[4*j+1] = x.y; q[4*j+2] = x.z; q[4*j+3] = x.w;
        ss += x.x*x.x + x.y*x.y + x.z*x.z + x.w*x.w;
    }
    ss *= 0.5f;

    float4 acc[16];
    #pragma unroll
    for (int j = 0; j < 16; j++) acc[j] = make_float4(0.f, 0.f, 0.f, 0.f);
    float accN = 0.0f;

    for (int m = 0; m < Mm; m++) {
        const float4* orow4 = (const float4*)(osh + m * Ff);
        float d0 = 0.f, d1 = 0.f, d2 = 0.f, d3 = 0.f;
        #pragma unroll
        for (int j = 0; j < 16; j++) {
            float4 o = orow4[j];                         // broadcast LDS
            d0 += o.x * q[4*j+0];
            d1 += o.y * q[4*j+1];
            d2 += o.z * q[4*j+2];
            d3 += o.w * q[4*j+3];
        }
        float dot = (d0 + d1) + (d2 + d3);
        float pp = __expf( dot - ss) + EPSf;
        float pm = __expf(-dot - ss) + EPSf;

        const float* kp = kvs + m * KV_PAD;              // 272B stride, 16B aligned
        const float* km = kvs + (m + Mm) * KV_PAD;
        #pragma unroll
        for (int j = 0; j < 16; j++) {
            float4 a = ((const float4*)kp)[j];           // broadcast LDS
            float4 c = ((const float4*)km)[j];
            acc[j].x += pp * a.x + pm * c.x;
            acc[j].y += pp * a.y + pm * c.y;
            acc[j].z += pp * a.z + pm * c.z;
            acc[j].w += pp * a.w + pm * c.w;
        }
        accN += pp * kp[Dd] + pm * km[Dd];
    }

    float inv = 1.0f / accN;
    float* orow = out + ((size_t)b * Tt + t) * Dd;
    #pragma unroll
    for (int j = 0; j < 16; j++) {
        float4 o;
        o.x = acc[j].x * inv;
        o.y = acc[j].y * inv;
        o.z = acc[j].z * inv;
        o.w = acc[j].w * inv;
        ((float4*)orow)[j] = o;
    }
}

// ---------------------------------------------------------------------------
// launch
// ---------------------------------------------------------------------------
extern "C" void kernel_launch(void* const* d_in, const int* in_sizes, int n_in,
                              void* d_out, int out_size) {
    const float* query = (const float*)d_in[0];
    const float* value = (const float*)d_in[1];
    const float* key   = (const float*)d_in[2];
    const float* omega = (const float*)d_in[3];
    float* out = (float*)d_out;

    static bool attr_set = false;
    const int smem_b = (TWO_M * KV_PAD + Mm * Ff) * sizeof(float);  // 102400
    if (!attr_set) {
        cudaFuncSetAttribute(out_kernel, cudaFuncAttributeMaxDynamicSharedMemorySize, smem_b);
        attr_set = true;
    }

    int nkv = Bb * TWO_M * (Dd + 1);
    zero_kv_kernel<<<(nkv + 255) / 256, 256>>>();
    kv_kernel<<<dim3(CHUNKS, Bb), 256>>>(key, value, omega);
    out_kernel<<<dim3(Tt / 256, Bb), 256, smem_b>>>(query, omega, out);
}

// round 4
// speedup vs baseline: 2.7454x; 2.7454x over previous
#include <cuda_runtime.h>
#include <math.h>
#include <stdint.h>

#define Bb 8
#define Tt 8192
#define Ss 8192
#define Ff 64
#define Dd 64
#define EPSf 1e-9f
#define KVPAD 72
#define ASPLITS 16
#define AROWS (Ss/ASPLITS)   /* 512 rows per block in kv kernel */

// kv scratch [b][256][72]; cols 65..71 stay zero
__device__ __align__(16) float g_kv[Bb * 256 * KVPAD];

// ---------------------------------------------------------------------------
// helpers
// ---------------------------------------------------------------------------
__device__ __forceinline__ float ftf32(float x) {
    unsigned u;
    asm("cvt.rna.tf32.f32 %0, %1;" : "=r"(u) : "f"(x));
    return __uint_as_float(u);
}

__device__ __forceinline__ void mma8(float4& d,
                                     float a0, float a1, float a2, float a3,
                                     float b0, float b1) {
    asm("mma.sync.aligned.m16n8k8.row.col.f32.tf32.tf32.f32 "
        "{%0,%1,%2,%3},{%4,%5,%6,%7},{%8,%9},{%0,%1,%2,%3};"
        : "+f"(d.x), "+f"(d.y), "+f"(d.z), "+f"(d.w)
        : "r"(__float_as_uint(a0)), "r"(__float_as_uint(a1)),
          "r"(__float_as_uint(a2)), "r"(__float_as_uint(a3)),
          "r"(__float_as_uint(b0)), "r"(__float_as_uint(b1)));
}

__global__ void zero_kv_kernel() {
    int i = blockIdx.x * blockDim.x + threadIdx.x;
    if (i < Bb * 256 * KVPAD) g_kv[i] = 0.0f;
}

// ---------------------------------------------------------------------------
// smem layouts (float offsets)
// ---------------------------------------------------------------------------
// kernel A
#define A_KS   0        /* [64][68]  */
#define A_VS   4352     /* [64][72]  */
#define A_PHT  8960     /* [256][68] */
#define A_OHI  26368    /* [128][68] */
#define A_OLO  35072    /* [128][68] */
#define A_SSH  43776    /* [64]      */
#define A_PRT  43840    /* [256]     */
#define A_TOT  44096
// kernel B
#define B_PHIQ 0        /* [128][260], aliases Qs/Ohi/Olo during phase 1 */
#define B_QS   0        /* [128][68]  */
#define B_OHI  8704     /* [128][68]  */
#define B_OLO  17408    /* [128][68]  */
#define B_KVS  33280    /* [256][72]  */
#define B_SSH  51712    /* [128]      */
#define B_PRT  51840    /* [256]      */
#define B_TOT  52096

extern __shared__ float sm[];

// ---------------------------------------------------------------------------
// Kernel A: fused  K -> phi_k -> kv partial (split-K over S, atomics)
// block: 256 thr / 8 warps.  Per 64-row chunk:
//   XW[64x128] = K_chunk . Omega^T   (split tf32: 3 mma passes)
//   PhT[256][64] = exp(+-XW - ss) + eps   (tf32-rounded, stored transposed)
//   acc[256x72] += PhT . V1_chunk
// ---------------------------------------------------------------------------
__global__ __launch_bounds__(256, 1)
void kv_kernel(const float* __restrict__ key,
               const float* __restrict__ value,
               const float* __restrict__ omega) {
    const int b   = blockIdx.y;
    const int tid = threadIdx.x;
    const int w   = tid >> 5;
    const int ln  = tid & 31;
    const int gid = ln >> 2;
    const int tq  = ln & 3;

    float* Ks  = sm + A_KS;
    float* Vs  = sm + A_VS;
    float* PhT = sm + A_PHT;
    float* Ohi = sm + A_OHI;
    float* Olo = sm + A_OLO;
    float* ssh = sm + A_SSH;
    float* prt = sm + A_PRT;

    // omega -> hi/lo tf32 split in smem
    for (int i = tid; i < 128 * 64; i += 256) {
        int m = i >> 6, f = i & 63;
        float x  = omega[i];
        float hi = ftf32(x);
        Ohi[m * 68 + f] = hi;
        Olo[m * 68 + f] = ftf32(x - hi);
    }

    float4 acc[2][9];
    #pragma unroll
    for (int mt = 0; mt < 2; mt++)
        #pragma unroll
        for (int nt = 0; nt < 9; nt++)
            acc[mt][nt] = make_float4(0.f, 0.f, 0.f, 0.f);

    const int row0base = blockIdx.x * AROWS;

    for (int c = 0; c < AROWS / 64; c++) {
        __syncthreads();   // previous-iter PhT reads done before overwrite
        const int row0 = row0base + c * 64;

        // ---- load K chunk (+ssq partials) and V chunk (tf32, +ones col) ----
        {
            int r = tid >> 2, qd = tid & 3;
            const float4* kg = (const float4*)(key + ((size_t)(b * Ss + row0 + r)) * Ff);
            float ps = 0.f;
            #pragma unroll
            for (int j = 0; j < 4; j++) {
                float4 x = kg[qd * 4 + j];
                ps += x.x * x.x + x.y * x.y + x.z * x.z + x.w * x.w;
                ((float4*)(Ks + r * 68))[qd * 4 + j] = x;
            }
            prt[tid] = ps;
            const float4* vg = (const float4*)(value + ((size_t)(b * Ss + row0 + r)) * Dd);
            #pragma unroll
            for (int j = 0; j < 4; j++) {
                float4 x = vg[qd * 4 + j];
                float4 y;
                y.x = ftf32(x.x); y.y = ftf32(x.y); y.z = ftf32(x.z); y.w = ftf32(x.w);
                ((float4*)(Vs + r * 72))[qd * 4 + j] = y;
            }
            if (tid < 64) {
                Vs[tid * 72 + 64] = 1.0f;
                #pragma unroll
                for (int p = 65; p < 72; p++) Vs[tid * 72 + p] = 0.0f;
            }
        }
        __syncthreads();
        if (tid < 64)
            ssh[tid] = 0.5f * (prt[tid * 4] + prt[tid * 4 + 1] +
                               prt[tid * 4 + 2] + prt[tid * 4 + 3]);
        __syncthreads();

        // ---- XW = K . Omega^T  (M=64 s-rows, warp w owns features [16w,16w+16)) ----
        float4 xw[4][2];
        #pragma unroll
        for (int mt = 0; mt < 4; mt++)
            #pragma unroll
            for (int nt = 0; nt < 2; nt++)
                xw[mt][nt] = make_float4(0.f, 0.f, 0.f, 0.f);

        for (int ks = 0; ks < 8; ks++) {
            int f0 = ks * 8 + tq;
            float bh[2][2], bl[2][2];
            #pragma unroll
            for (int nt = 0; nt < 2; nt++) {
                int m = w * 16 + nt * 8 + gid;
                bh[nt][0] = Ohi[m * 68 + f0];     bh[nt][1] = Ohi[m * 68 + f0 + 4];
                bl[nt][0] = Olo[m * 68 + f0];     bl[nt][1] = Olo[m * 68 + f0 + 4];
            }
            #pragma unroll
            for (int mt = 0; mt < 4; mt++) {
                int s = mt * 16 + gid;
                float a0 = Ks[s * 68 + f0],       a1 = Ks[(s + 8) * 68 + f0];
                float a2 = Ks[s * 68 + f0 + 4],   a3 = Ks[(s + 8) * 68 + f0 + 4];
                float h0 = ftf32(a0), h1 = ftf32(a1), h2 = ftf32(a2), h3 = ftf32(a3);
                float l0 = ftf32(a0 - h0), l1 = ftf32(a1 - h1);
                float l2 = ftf32(a2 - h2), l3 = ftf32(a3 - h3);
                #pragma unroll
                for (int nt = 0; nt < 2; nt++) {
                    mma8(xw[mt][nt], h0, h1, h2, h3, bh[nt][0], bh[nt][1]);
                    mma8(xw[mt][nt], l0, l1, l2, l3, bh[nt][0], bh[nt][1]);
                    mma8(xw[mt][nt], h0, h1, h2, h3, bl[nt][0], bl[nt][1]);
                }
            }
        }

        // ---- phi epilogue: PhT[m][s] = tf32(exp(+-xw - ss) + eps) ----
        #pragma unroll
        for (int mt = 0; mt < 4; mt++) {
            int s0 = mt * 16 + gid;
            float ssa = ssh[s0], ssb = ssh[s0 + 8];
            #pragma unroll
            for (int nt = 0; nt < 2; nt++) {
                int m0 = w * 16 + nt * 8 + 2 * tq;
                float4 v = xw[mt][nt];
                PhT[m0 * 68 + s0]             = ftf32(__expf( v.x - ssa) + EPSf);
                PhT[(m0 + 1) * 68 + s0]       = ftf32(__expf( v.y - ssa) + EPSf);
                PhT[m0 * 68 + s0 + 8]         = ftf32(__expf( v.z - ssb) + EPSf);
                PhT[(m0 + 1) * 68 + s0 + 8]   = ftf32(__expf( v.w - ssb) + EPSf);
                PhT[(m0 + 128) * 68 + s0]     = ftf32(__expf(-v.x - ssa) + EPSf);
                PhT[(m0 + 129) * 68 + s0]     = ftf32(__expf(-v.y - ssa) + EPSf);
                PhT[(m0 + 128) * 68 + s0 + 8] = ftf32(__expf(-v.z - ssb) + EPSf);
                PhT[(m0 + 129) * 68 + s0 + 8] = ftf32(__expf(-v.w - ssb) + EPSf);
            }
        }
        __syncthreads();

        // ---- acc += PhT . V1   (warp w owns kv rows [32w, 32w+32)) ----
        #pragma unroll 2
        for (int ks = 0; ks < 8; ks++) {
            float a[2][4];
            #pragma unroll
            for (int mt = 0; mt < 2; mt++) {
                int mr = 32 * w + mt * 16 + gid;
                int sc = ks * 8 + tq;
                a[mt][0] = PhT[mr * 68 + sc];
                a[mt][1] = PhT[(mr + 8) * 68 + sc];
                a[mt][2] = PhT[mr * 68 + sc + 4];
                a[mt][3] = PhT[(mr + 8) * 68 + sc + 4];
            }
            #pragma unroll
            for (int nt = 0; nt < 9; nt++) {
                float b0 = Vs[(ks * 8 + tq) * 72 + nt * 8 + gid];
                float b1 = Vs[(ks * 8 + tq + 4) * 72 + nt * 8 + gid];
                #pragma unroll
                for (int mt = 0; mt < 2; mt++)
                    mma8(acc[mt][nt], a[mt][0], a[mt][1], a[mt][2], a[mt][3], b0, b1);
            }
        }
    }

    // ---- atomic reduce into g_kv ----
    float* gp = g_kv + (size_t)b * 256 * KVPAD;
    #pragma unroll
    for (int mt = 0; mt < 2; mt++) {
        int m0 = 32 * w + mt * 16 + gid;
        #pragma unroll
        for (int nt = 0; nt < 9; nt++) {
            int d0 = nt * 8 + 2 * tq;
            atomicAdd(gp + m0 * KVPAD + d0,           acc[mt][nt].x);
            atomicAdd(gp + m0 * KVPAD + d0 + 1,       acc[mt][nt].y);
            atomicAdd(gp + (m0 + 8) * KVPAD + d0,     acc[mt][nt].z);
            atomicAdd(gp + (m0 + 8) * KVPAD + d0 + 1, acc[mt][nt].w);
        }
    }
}

// ---------------------------------------------------------------------------
// Kernel B: fused  Q -> phi_q -> out = (phi_q . kv) / normalizer
// block: 256 thr / 8 warps, 128 t-rows per block.
// ---------------------------------------------------------------------------
__global__ __launch_bounds__(256, 1)
void out_kernel(const float* __restrict__ query,
                const float* __restrict__ omega,
                float* __restrict__ outp) {
    const int b   = blockIdx.y;
    const int t0  = blockIdx.x * 128;
    const int tid = threadIdx.x;
    const int w   = tid >> 5;
    const int ln  = tid & 31;
    const int gid = ln >> 2;
    const int tq  = ln & 3;

    float* PhiQ = sm + B_PHIQ;
    float* Qs   = sm + B_QS;
    float* Ohi  = sm + B_OHI;
    float* Olo  = sm + B_OLO;
    float* kvs  = sm + B_KVS;
    float* ssh  = sm + B_SSH;
    float* prt  = sm + B_PRT;

    // ---- phase-1 loads: Q tile, omega hi/lo, kv (tf32-rounded) ----
    {
        int r = tid >> 1, h = tid & 1;
        const float4* qg = (const float4*)(query + ((size_t)(b * Tt + t0 + r)) * Ff);
        float ps = 0.f;
        #pragma unroll
        for (int j = 0; j < 8; j++) {
            float4 x = qg[h * 8 + j];
            ps += x.x * x.x + x.y * x.y + x.z * x.z + x.w * x.w;
            ((float4*)(Qs + r * 68))[h * 8 + j] = x;
        }
        prt[tid] = ps;
    }
    for (int i = tid; i < 128 * 64; i += 256) {
        int m = i >> 6, f = i & 63;
        float x  = omega[i];
        float hi = ftf32(x);
        Ohi[m * 68 + f] = hi;
        Olo[m * 68 + f] = ftf32(x - hi);
    }
    {
        const float4* gk = (const float4*)(g_kv + (size_t)b * 256 * KVPAD);
        for (int i = tid; i < 256 * KVPAD / 4; i += 256) {
            float4 x = gk[i];
            float4 y;
            y.x = ftf32(x.x); y.y = ftf32(x.y); y.z = ftf32(x.z); y.w = ftf32(x.w);
            ((float4*)kvs)[i] = y;
        }
    }
    __syncthreads();
    if (tid < 128) ssh[tid] = 0.5f * (prt[2 * tid] + prt[2 * tid + 1]);
    __syncthreads();

    // ---- XW = Q . Omega^T  (M=128 t-rows, warp w owns features [16w,16w+16)) ----
    float4 xw[8][2];
    #pragma unroll
    for (int mt = 0; mt < 8; mt++)
        #pragma unroll
        for (int nt = 0; nt < 2; nt++)
            xw[mt][nt] = make_float4(0.f, 0.f, 0.f, 0.f);

    for (int ks = 0; ks < 8; ks++) {
        int f0 = ks * 8 + tq;
        float bh[2][2], bl[2][2];
        #pragma unroll
        for (int nt = 0; nt < 2; nt++) {
            int m = w * 16 + nt * 8 + gid;
            bh[nt][0] = Ohi[m * 68 + f0];   bh[nt][1] = Ohi[m * 68 + f0 + 4];
            bl[nt][0] = Olo[m * 68 + f0];   bl[nt][1] = Olo[m * 68 + f0 + 4];
        }
        #pragma unroll
        for (int mt = 0; mt < 8; mt++) {
            int t = mt * 16 + gid;
            float a0 = Qs[t * 68 + f0],       a1 = Qs[(t + 8) * 68 + f0];
            float a2 = Qs[t * 68 + f0 + 4],   a3 = Qs[(t + 8) * 68 + f0 + 4];
            float h0 = ftf32(a0), h1 = ftf32(a1), h2 = ftf32(a2), h3 = ftf32(a3);
            float l0 = ftf32(a0 - h0), l1 = ftf32(a1 - h1);
            float l2 = ftf32(a2 - h2), l3 = ftf32(a3 - h3);
            #pragma unroll
            for (int nt = 0; nt < 2; nt++) {
                mma8(xw[mt][nt], h0, h1, h2, h3, bh[nt][0], bh[nt][1]);
                mma8(xw[mt][nt], l0, l1, l2, l3, bh[nt][0], bh[nt][1]);
                mma8(xw[mt][nt], h0, h1, h2, h3, bl[nt][0], bl[nt][1]);
            }
        }
    }
    __syncthreads();   // all Qs/omega reads done; PhiQ may overwrite them now

    // ---- phi epilogue: PhiQ[t][m] = tf32(exp(+-xw - ss) + eps) ----
    #pragma unroll
    for (int mt = 0; mt < 8; mt++) {
        int t = mt * 16 + gid;
        float ssa = ssh[t], ssb = ssh[t + 8];
        #pragma unroll
        for (int nt = 0; nt < 2; nt++) {
            int m0 = w * 16 + nt * 8 + 2 * tq;
            float4 v = xw[mt][nt];
            PhiQ[t * 260 + m0]             = ftf32(__expf( v.x - ssa) + EPSf);
            PhiQ[t * 260 + m0 + 1]         = ftf32(__expf( v.y - ssa) + EPSf);
            PhiQ[(t + 8) * 260 + m0]       = ftf32(__expf( v.z - ssb) + EPSf);
            PhiQ[(t + 8) * 260 + m0 + 1]   = ftf32(__expf( v.w - ssb) + EPSf);
            PhiQ[t * 260 + m0 + 128]       = ftf32(__expf(-v.x - ssa) + EPSf);
            PhiQ[t * 260 + m0 + 129]       = ftf32(__expf(-v.y - ssa) + EPSf);
            PhiQ[(t + 8) * 260 + m0 + 128] = ftf32(__expf(-v.z - ssb) + EPSf);
            PhiQ[(t + 8) * 260 + m0 + 129] = ftf32(__expf(-v.w - ssb) + EPSf);
        }
    }
    __syncthreads();

    // ---- out = PhiQ . kv  (warp w owns t-rows [16w,16w+16), K=256) ----
    float4 oacc[9];
    #pragma unroll
    for (int nt = 0; nt < 9; nt++) oacc[nt] = make_float4(0.f, 0.f, 0.f, 0.f);

    #pragma unroll 4
    for (int ks = 0; ks < 32; ks++) {
        int tr = 16 * w + gid;
        int mc = ks * 8 + tq;
        float a0 = PhiQ[tr * 260 + mc],       a1 = PhiQ[(tr + 8) * 260 + mc];
        float a2 = PhiQ[tr * 260 + mc + 4],   a3 = PhiQ[(tr + 8) * 260 + mc + 4];
        #pragma unroll
        for (int nt = 0; nt < 9; nt++) {
            float b0 = kvs[(ks * 8 + tq) * KVPAD + nt * 8 + gid];
            float b1 = kvs[(ks * 8 + tq + 4) * KVPAD + nt * 8 + gid];
            mma8(oacc[nt], a0, a1, a2, a3, b0, b1);
        }
    }

    // ---- normalize (normalizer col 64 lives in n-tile 8, lanes tq==0) ----
    float n0 = __shfl_sync(0xffffffffu, oacc[8].x, ln & ~3);
    float n1 = __shfl_sync(0xffffffffu, oacc[8].z, ln & ~3);
    float inv0 = 1.0f / n0;
    float inv1 = 1.0f / n1;

    size_t orow = ((size_t)b * Tt + t0 + 16 * w + gid) * 64;
    #pragma unroll
    for (int nt = 0; nt < 8; nt++) {
        int col = nt * 8 + 2 * tq;
        float2 r0 = make_float2(oacc[nt].x * inv0, oacc[nt].y * inv0);
        float2 r1 = make_float2(oacc[nt].z * inv1, oacc[nt].w * inv1);
        *(float2*)(outp + orow + col)          = r0;
        *(float2*)(outp + orow + 8 * 64 + col) = r1;
    }
}

// ---------------------------------------------------------------------------
// launch
// ---------------------------------------------------------------------------
extern "C" void kernel_launch(void* const* d_in, const int* in_sizes, int n_in,
                              void* d_out, int out_size) {
    const float* query = (const float*)d_in[0];
    const float* value = (const float*)d_in[1];
    const float* key   = (const float*)d_in[2];
    const float* omega = (const float*)d_in[3];
    float* out = (float*)d_out;

    cudaFuncSetAttribute(kv_kernel,  cudaFuncAttributeMaxDynamicSharedMemorySize,
                         A_TOT * (int)sizeof(float));
    cudaFuncSetAttribute(out_kernel, cudaFuncAttributeMaxDynamicSharedMemorySize,
                         B_TOT * (int)sizeof(float));

    zero_kv_kernel<<<(Bb * 256 * KVPAD + 255) / 256, 256>>>();
    kv_kernel<<<dim3(ASPLITS, Bb), 256, A_TOT * sizeof(float)>>>(key, value, omega);
    out_kernel<<<dim3(Tt / 128, Bb), 256, B_TOT * sizeof(float)>>>(query, omega, out);
}